// round 1
// baseline (speedup 1.0000x reference)
#include <cuda_runtime.h>
#include <math.h>

#define BATCH 4
#define CCH   512
#define HCH   64
#define NPIX  4096

// Scratch (device globals — no allocation allowed)
__device__ __align__(16) float g_fgh[3 * BATCH * HCH * NPIX];  // f,g,h projections
__device__ __align__(16) float g_o[BATCH * HCH * NPIX];        // attention output o
__device__ float g_invsig[4];                                  // 1/sigma per weight

// ---------------------------------------------------------------------------
// Spectral norm: sigma = || W @ normalize(W^T u) ||_2  (exact reduction of the
// reference power-iteration step). One block per weight matrix.
// ---------------------------------------------------------------------------
__global__ void spectral_kernel(const float* __restrict__ Wf, const float* __restrict__ Wg,
                                const float* __restrict__ Wh, const float* __restrict__ Wv,
                                const float* __restrict__ uf, const float* __restrict__ ug,
                                const float* __restrict__ uh, const float* __restrict__ uv)
{
    __shared__ float u_s[512];
    __shared__ float v_s[512];
    __shared__ float red[512];
    int w = blockIdx.x;
    const float* W; const float* u; int R, Cc;
    if (w == 0)      { W = Wf; u = uf; R = HCH; Cc = CCH; }
    else if (w == 1) { W = Wg; u = ug; R = HCH; Cc = CCH; }
    else if (w == 2) { W = Wh; u = uh; R = HCH; Cc = CCH; }
    else             { W = Wv; u = uv; R = CCH; Cc = HCH; }
    int t = threadIdx.x;  // 512 threads
    if (t < R) u_s[t] = u[t];
    __syncthreads();
    float v = 0.f;
    if (t < Cc) {
        for (int r = 0; r < R; ++r) v += W[r * Cc + t] * u_s[r];
    }
    red[t] = (t < Cc) ? v * v : 0.f;
    __syncthreads();
    for (int s = 256; s > 0; s >>= 1) {
        if (t < s) red[t] += red[t + s];
        __syncthreads();
    }
    float rn = rsqrtf(fmaxf(red[0], 1e-24f));
    if (t < Cc) v_s[t] = v * rn;
    __syncthreads();
    float tv = 0.f;
    if (t < R) {
        const float* row = W + t * Cc;
        for (int c = 0; c < Cc; ++c) tv += row[c] * v_s[c];
    }
    red[t] = (t < R) ? tv * tv : 0.f;
    __syncthreads();
    for (int s = 256; s > 0; s >>= 1) {
        if (t < s) red[t] += red[t + s];
        __syncthreads();
    }
    if (t == 0) g_invsig[w] = rsqrtf(fmaxf(red[0], 1e-24f));
}

// ---------------------------------------------------------------------------
// Projections f,g,h = (W/sigma) @ x + b.  Tile: [64 rows x 128 pixels], K=16.
// grid (N/128, B, 3), 256 threads, 8x4 register tile per thread.
// ---------------------------------------------------------------------------
__global__ void __launch_bounds__(256) proj_kernel(
    const float* __restrict__ x,
    const float* __restrict__ Wf, const float* __restrict__ Wg, const float* __restrict__ Wh,
    const float* __restrict__ bf, const float* __restrict__ bg, const float* __restrict__ bh)
{
    __shared__ __align__(16) float W_s[16 * 64];
    __shared__ __align__(16) float X_s[16 * 128];
    int nb = blockIdx.x, b = blockIdx.y, w = blockIdx.z;
    const float* W    = (w == 0) ? Wf : ((w == 1) ? Wg : Wh);
    const float* bias = (w == 0) ? bf : ((w == 1) ? bg : bh);
    float invs = g_invsig[w];
    int tid = threadIdx.x;
    int tr = tid >> 5, tc = tid & 31;
    int n0 = nb * 128;
    const float* xb = x + (size_t)b * CCH * NPIX;
    float acc[8][4];
#pragma unroll
    for (int i = 0; i < 8; i++)
#pragma unroll
        for (int j = 0; j < 4; j++) acc[i][j] = 0.f;

    int wrow = tid >> 2, wcg = tid & 3;
    for (int c0 = 0; c0 < CCH; c0 += 16) {
        float4 wv = *(const float4*)&W[wrow * CCH + c0 + wcg * 4];
        W_s[(wcg * 4 + 0) * 64 + wrow] = wv.x;
        W_s[(wcg * 4 + 1) * 64 + wrow] = wv.y;
        W_s[(wcg * 4 + 2) * 64 + wrow] = wv.z;
        W_s[(wcg * 4 + 3) * 64 + wrow] = wv.w;
#pragma unroll
        for (int i = 0; i < 2; ++i) {
            int idx = tid + i * 256;
            int row = idx >> 5, c4 = idx & 31;
            *(float4*)&X_s[row * 128 + c4 * 4] =
                *(const float4*)&xb[(size_t)(c0 + row) * NPIX + n0 + c4 * 4];
        }
        __syncthreads();
#pragma unroll
        for (int kc = 0; kc < 16; ++kc) {
            float4 xa = *(const float4*)&X_s[kc * 128 + tc * 4];
            float4 wa = *(const float4*)&W_s[kc * 64 + tr * 8];
            float4 wb = *(const float4*)&W_s[kc * 64 + tr * 8 + 4];
            float wreg[8] = {wa.x, wa.y, wa.z, wa.w, wb.x, wb.y, wb.z, wb.w};
#pragma unroll
            for (int rr = 0; rr < 8; ++rr) {
                acc[rr][0] += wreg[rr] * xa.x;
                acc[rr][1] += wreg[rr] * xa.y;
                acc[rr][2] += wreg[rr] * xa.z;
                acc[rr][3] += wreg[rr] * xa.w;
            }
        }
        __syncthreads();
    }
    float* outp = g_fgh + (size_t)(w * BATCH + b) * HCH * NPIX;
#pragma unroll
    for (int rr = 0; rr < 8; ++rr) {
        int r = tr * 8 + rr;
        float bb = bias[r];
        float4 o;
        o.x = acc[rr][0] * invs + bb;
        o.y = acc[rr][1] * invs + bb;
        o.z = acc[rr][2] * invs + bb;
        o.w = acc[rr][3] * invs + bb;
        *(float4*)&outp[(size_t)r * NPIX + n0 + tc * 4] = o;
    }
}

// ---------------------------------------------------------------------------
// Flash attention: per block, 64 queries; loop over 64-key tiles with online
// softmax.  S = F^T G, O += P H^T, all fp32 FFMA, 4x4 register tiles.
// grid (N/64, B), 256 threads.
// ---------------------------------------------------------------------------
__global__ void __launch_bounds__(256) attn_kernel()
{
    extern __shared__ float smdyn[];
    float* F_s = smdyn;                  // [64][64]  (k-major)
    float* G_s = smdyn + 64 * 64;        // [64][64]  (k-major)
    float* HT  = smdyn + 2 * 64 * 64;    // [64][68]  ([m][kd], padded)
    float* PT  = HT + 64 * 68;           // [64][68]  ([m][n],  padded)

    int qt = blockIdx.x, b = blockIdx.y;
    int tid = threadIdx.x;
    int tn = tid >> 4, tm = tid & 15;
    const float* fptr = g_fgh + (size_t)(0 * BATCH + b) * HCH * NPIX;
    const float* gptr = g_fgh + (size_t)(1 * BATCH + b) * HCH * NPIX;
    const float* hptr = g_fgh + (size_t)(2 * BATCH + b) * HCH * NPIX;
    int n0 = qt * 64;

#pragma unroll
    for (int i = 0; i < 4; ++i) {
        int idx = tid + i * 256;
        int row = idx >> 4, c4 = idx & 15;
        *(float4*)&F_s[row * 64 + c4 * 4] =
            *(const float4*)&fptr[(size_t)row * NPIX + n0 + c4 * 4];
    }

    float oacc[4][4];
#pragma unroll
    for (int i = 0; i < 4; i++)
#pragma unroll
        for (int j = 0; j < 4; j++) oacc[i][j] = 0.f;
    float mrow[4] = {-1e30f, -1e30f, -1e30f, -1e30f};
    float lrow[4] = {0.f, 0.f, 0.f, 0.f};

    for (int kt = 0; kt < 64; ++kt) {
        int m0 = kt * 64;
        __syncthreads();  // protect G_s/HT/PT from previous iteration readers
#pragma unroll
        for (int i = 0; i < 4; ++i) {
            int idx = tid + i * 256;
            int row = idx >> 4, c4 = idx & 15;
            *(float4*)&G_s[row * 64 + c4 * 4] =
                *(const float4*)&gptr[(size_t)row * NPIX + m0 + c4 * 4];
            float4 hv = *(const float4*)&hptr[(size_t)row * NPIX + m0 + c4 * 4];
            HT[(c4 * 4 + 0) * 68 + row] = hv.x;
            HT[(c4 * 4 + 1) * 68 + row] = hv.y;
            HT[(c4 * 4 + 2) * 68 + row] = hv.z;
            HT[(c4 * 4 + 3) * 68 + row] = hv.w;
        }
        __syncthreads();

        float s[4][4];
#pragma unroll
        for (int i = 0; i < 4; i++)
#pragma unroll
            for (int j = 0; j < 4; j++) s[i][j] = 0.f;
#pragma unroll 8
        for (int k = 0; k < 64; ++k) {
            float4 fa = *(const float4*)&F_s[k * 64 + tn * 4];
            float4 ga = *(const float4*)&G_s[k * 64 + tm * 4];
            float fv[4] = {fa.x, fa.y, fa.z, fa.w};
            float gv[4] = {ga.x, ga.y, ga.z, ga.w};
#pragma unroll
            for (int i = 0; i < 4; i++)
#pragma unroll
                for (int j = 0; j < 4; j++) s[i][j] += fv[i] * gv[j];
        }

        // online softmax (rows split across 16 lanes: same-tn half-warps)
#pragma unroll
        for (int i = 0; i < 4; ++i) {
            float mx = fmaxf(fmaxf(s[i][0], s[i][1]), fmaxf(s[i][2], s[i][3]));
#pragma unroll
            for (int off = 8; off > 0; off >>= 1)
                mx = fmaxf(mx, __shfl_xor_sync(0xffffffffu, mx, off));
            float mnew = fmaxf(mrow[i], mx);
            float corr = __expf(mrow[i] - mnew);
            float p0 = __expf(s[i][0] - mnew);
            float p1 = __expf(s[i][1] - mnew);
            float p2 = __expf(s[i][2] - mnew);
            float p3 = __expf(s[i][3] - mnew);
            float ls = p0 + p1 + p2 + p3;
#pragma unroll
            for (int off = 8; off > 0; off >>= 1)
                ls += __shfl_xor_sync(0xffffffffu, ls, off);
            lrow[i] = lrow[i] * corr + ls;
            mrow[i] = mnew;
            oacc[i][0] *= corr; oacc[i][1] *= corr;
            oacc[i][2] *= corr; oacc[i][3] *= corr;
            PT[(tm * 4 + 0) * 68 + tn * 4 + i] = p0;
            PT[(tm * 4 + 1) * 68 + tn * 4 + i] = p1;
            PT[(tm * 4 + 2) * 68 + tn * 4 + i] = p2;
            PT[(tm * 4 + 3) * 68 + tn * 4 + i] = p3;
        }
        __syncthreads();

#pragma unroll 8
        for (int m = 0; m < 64; ++m) {
            float4 pa = *(const float4*)&PT[m * 68 + tn * 4];
            float4 ha = *(const float4*)&HT[m * 68 + tm * 4];
            float pv[4] = {pa.x, pa.y, pa.z, pa.w};
            float hv[4] = {ha.x, ha.y, ha.z, ha.w};
#pragma unroll
            for (int i = 0; i < 4; i++)
#pragma unroll
                for (int j = 0; j < 4; j++) oacc[i][j] += pv[i] * hv[j];
        }
    }

    float* ob = g_o + (size_t)b * HCH * NPIX;
#pragma unroll
    for (int i = 0; i < 4; ++i) {
        float inv = 1.f / lrow[i];
#pragma unroll
        for (int j = 0; j < 4; ++j) {
            ob[(size_t)(tm * 4 + j) * NPIX + n0 + tn * 4 + i] = oacc[i][j] * inv;
        }
    }
}

// ---------------------------------------------------------------------------
// Output projection + residual: out = gamma*((Wv/sigma) @ o + bv) + x
// grid (N/128, C/64, B), 256 threads, same tiling as proj_kernel.
// ---------------------------------------------------------------------------
__global__ void __launch_bounds__(256) outproj_kernel(
    const float* __restrict__ x, const float* __restrict__ Wv,
    const float* __restrict__ bv, const float* __restrict__ gamma,
    float* __restrict__ out)
{
    __shared__ __align__(16) float W_s[16 * 64];
    __shared__ __align__(16) float O_s[16 * 128];
    int nb = blockIdx.x, ct = blockIdx.y, b = blockIdx.z;
    int tid = threadIdx.x;
    int tr = tid >> 5, tc = tid & 31;
    int n0 = nb * 128, c0 = ct * 64;
    const float* ob = g_o + (size_t)b * HCH * NPIX;
    float invs = g_invsig[3];
    float gm = gamma[0];
    float acc[8][4];
#pragma unroll
    for (int i = 0; i < 8; i++)
#pragma unroll
        for (int j = 0; j < 4; j++) acc[i][j] = 0.f;

    int wrow = tid >> 2, wkg = tid & 3;
    for (int k0 = 0; k0 < HCH; k0 += 16) {
        float4 wv4 = *(const float4*)&Wv[(size_t)(c0 + wrow) * HCH + k0 + wkg * 4];
        W_s[(wkg * 4 + 0) * 64 + wrow] = wv4.x;
        W_s[(wkg * 4 + 1) * 64 + wrow] = wv4.y;
        W_s[(wkg * 4 + 2) * 64 + wrow] = wv4.z;
        W_s[(wkg * 4 + 3) * 64 + wrow] = wv4.w;
#pragma unroll
        for (int i = 0; i < 2; ++i) {
            int idx = tid + i * 256;
            int row = idx >> 5, c4 = idx & 31;
            *(float4*)&O_s[row * 128 + c4 * 4] =
                *(const float4*)&ob[(size_t)(k0 + row) * NPIX + n0 + c4 * 4];
        }
        __syncthreads();
#pragma unroll
        for (int kc = 0; kc < 16; ++kc) {
            float4 xa = *(const float4*)&O_s[kc * 128 + tc * 4];
            float4 wa = *(const float4*)&W_s[kc * 64 + tr * 8];
            float4 wb = *(const float4*)&W_s[kc * 64 + tr * 8 + 4];
            float wreg[8] = {wa.x, wa.y, wa.z, wa.w, wb.x, wb.y, wb.z, wb.w};
#pragma unroll
            for (int rr = 0; rr < 8; ++rr) {
                acc[rr][0] += wreg[rr] * xa.x;
                acc[rr][1] += wreg[rr] * xa.y;
                acc[rr][2] += wreg[rr] * xa.z;
                acc[rr][3] += wreg[rr] * xa.w;
            }
        }
        __syncthreads();
    }
#pragma unroll
    for (int rr = 0; rr < 8; ++rr) {
        int c = c0 + tr * 8 + rr;
        float bb = bv[c];
        size_t base = ((size_t)b * CCH + c) * NPIX + n0 + tc * 4;
        float4 xv = *(const float4*)&x[base];
        float4 o;
        o.x = gm * (acc[rr][0] * invs + bb) + xv.x;
        o.y = gm * (acc[rr][1] * invs + bb) + xv.y;
        o.z = gm * (acc[rr][2] * invs + bb) + xv.z;
        o.w = gm * (acc[rr][3] * invs + bb) + xv.w;
        *(float4*)&out[base] = o;
    }
}

// ---------------------------------------------------------------------------
extern "C" void kernel_launch(void* const* d_in, const int* in_sizes, int n_in,
                              void* d_out, int out_size)
{
    const float* x     = (const float*)d_in[0];
    const float* Wf    = (const float*)d_in[1];
    const float* bf    = (const float*)d_in[2];
    const float* Wg    = (const float*)d_in[3];
    const float* bg    = (const float*)d_in[4];
    const float* Wh    = (const float*)d_in[5];
    const float* bh    = (const float*)d_in[6];
    const float* Wv    = (const float*)d_in[7];
    const float* bv    = (const float*)d_in[8];
    const float* uf    = (const float*)d_in[9];
    const float* ug    = (const float*)d_in[10];
    const float* uh    = (const float*)d_in[11];
    const float* uv    = (const float*)d_in[12];
    const float* gamma = (const float*)d_in[13];
    float* out = (float*)d_out;

    const int smem_attn = (64 * 64 * 2 + 64 * 68 * 2) * (int)sizeof(float);  // 67584 B
    cudaFuncSetAttribute(attn_kernel, cudaFuncAttributeMaxDynamicSharedMemorySize, smem_attn);

    spectral_kernel<<<4, 512>>>(Wf, Wg, Wh, Wv, uf, ug, uh, uv);
    proj_kernel<<<dim3(NPIX / 128, BATCH, 3), 256>>>(x, Wf, Wg, Wh, bf, bg, bh);
    attn_kernel<<<dim3(NPIX / 64, BATCH), 256, smem_attn>>>();
    outproj_kernel<<<dim3(NPIX / 128, CCH / 64, BATCH), 256>>>(x, Wv, bv, gamma, out);
}